// round 1
// baseline (speedup 1.0000x reference)
#include <cuda_runtime.h>
#include <cstdint>

#define CB 256      // channels
#define TB 1024     // time steps
#define BB 4        // batch

typedef unsigned long long u64;

// ---- packed fp32x2 helpers (Blackwell) ----
__device__ __forceinline__ u64 dup2(float v) {
    u64 r;
    asm("mov.b64 %0, {%1, %1};" : "=l"(r) : "f"(v));
    return r;
}
__device__ __forceinline__ void unpack2(u64 p, float &lo, float &hi) {
    asm("mov.b64 {%0, %1}, %2;" : "=f"(lo), "=f"(hi) : "l"(p));
}
__device__ __forceinline__ u64 ffma2(u64 a, u64 b, u64 c) {
    u64 d;
    asm("fma.rn.f32x2 %0, %1, %2, %3;" : "=l"(d) : "l"(a), "l"(b), "l"(c));
    return d;
}
__device__ __forceinline__ float ex2f(float v) {
    float y;
    asm("ex2.approx.ftz.f32 %0, %1;" : "=f"(y) : "f"(v));
    return y;
}

// One CTA per (b, t). Thread c owns channel c.
// framed[b,c,t,d] = xs[b,c, t-31+d] (zero-padded), d in [0,32)
// q/k[c,s] = relu( framed[c,:] . Wfold[s,:] + bfold[s] )
// ssa[i,j] = scale * sum_s q[i,s] k[j,s];  attn = softmax_j;  att[i] = sum_j attn[i,j] xs[j,t]
// out = x + att
__global__ void __launch_bounds__(256, 2)
csa_kernel(const float* __restrict__ x,
           const float* __restrict__ kw,  const float* __restrict__ kbias,
           const float* __restrict__ kg,  const float* __restrict__ kbeta,
           const float* __restrict__ qw,  const float* __restrict__ qbias,
           const float* __restrict__ qg,  const float* __restrict__ qbeta,
           float* __restrict__ out)
{
    __shared__ __align__(16) float s_wq[32 * 32];   // folded query weights [s][d]
    __shared__ __align__(16) float s_wk[32 * 32];   // folded key   weights [s][d]
    __shared__ float s_bq[32];
    __shared__ float s_bk[32];
    // k in pair layout: [j2][s][p] with p -> channel j = 2*j2 + p, row stride 68 floats
    // (68*4 = 272 B = 17*16 -> every (j2, even s) float4 is 16B aligned)
    __shared__ __align__(16) float s_kp[128 * 68];
    __shared__ __align__(8)  float s_v[256];        // xs[b, j, t]

    const int t = blockIdx.x;
    const int b = blockIdx.y;
    const int c = threadIdx.x;

    // ---- fold BN into weights/bias ----
    const float inv = rsqrtf(1.0f + 1e-5f);
    for (int idx = c; idx < 32 * 32; idx += 256) {
        int s = idx >> 5;
        s_wq[idx] = qw[idx] * (qg[s] * inv);
        s_wk[idx] = kw[idx] * (kg[s] * inv);
    }
    if (c < 32) {
        s_bq[c] = qbias[c] * (qg[c] * inv) + qbeta[c];
        s_bk[c] = kbias[c] * (kg[c] * inv) + kbeta[c];
    }

    // ---- load causal window into registers (x fits in L2) ----
    float win[32];
    const float* xrow = x + ((size_t)(b * CB + c)) * TB;
    #pragma unroll
    for (int d = 0; d < 32; d++) {
        int tau = t - 31 + d;
        win[d] = (tau >= 0) ? xrow[tau] : 0.0f;
    }
    s_v[c] = win[31];
    __syncthreads();

    // ---- key projection -> smem pair layout ----
    {
        float* kdst = s_kp + (c >> 1) * 68 + (c & 1);
        #pragma unroll
        for (int s = 0; s < 32; s++) {
            float acc = s_bk[s];
            const float4* wr = (const float4*)(s_wk + s * 32);
            #pragma unroll
            for (int d4 = 0; d4 < 8; d4++) {
                float4 w4 = wr[d4];
                acc += win[4 * d4 + 0] * w4.x;
                acc += win[4 * d4 + 1] * w4.y;
                acc += win[4 * d4 + 2] * w4.z;
                acc += win[4 * d4 + 3] * w4.w;
            }
            kdst[2 * s] = fmaxf(acc, 0.0f);
        }
    }

    // ---- query projection -> duplicated packed registers ----
    // fold attention scale AND log2(e) into q so scores are in log2 domain
    u64 qq[32];
    const float qscale = 0.17677669529663687f * 1.4426950408889634f; // (1/sqrt(32)) * log2(e)
    #pragma unroll
    for (int s = 0; s < 32; s++) {
        float acc = s_bq[s];
        const float4* wr = (const float4*)(s_wq + s * 32);
        #pragma unroll
        for (int d4 = 0; d4 < 8; d4++) {
            float4 w4 = wr[d4];
            acc += win[4 * d4 + 0] * w4.x;
            acc += win[4 * d4 + 1] * w4.y;
            acc += win[4 * d4 + 2] * w4.z;
            acc += win[4 * d4 + 3] * w4.w;
        }
        qq[s] = dup2(fmaxf(acc, 0.0f) * qscale);
    }
    __syncthreads();

    // ---- ssa (packed f32x2) + online softmax (base 2) + weighted sum ----
    float m = -1e30f, den = 0.0f, num = 0.0f;
    #pragma unroll 1
    for (int j2 = 0; j2 < 128; j2++) {
        const ulonglong2* kp = (const ulonglong2*)(s_kp + j2 * 68);
        u64 acc = 0ull;  // packed (0.0f, 0.0f)
        #pragma unroll
        for (int s2 = 0; s2 < 16; s2++) {
            ulonglong2 kk = kp[s2];          // LDS.128: {k[j0,s],k[j1,s]},{k[j0,s+1],k[j1,s+1]}
            acc = ffma2(qq[2 * s2 + 0], kk.x, acc);
            acc = ffma2(qq[2 * s2 + 1], kk.y, acc);
        }
        float sc0, sc1;
        unpack2(acc, sc0, sc1);              // log2-domain scores for j0, j1
        float2 v2 = *(const float2*)(s_v + 2 * j2);
        float mx   = fmaxf(m, fmaxf(sc0, sc1));
        float corr = ex2f(m - mx);
        float e0   = ex2f(sc0 - mx);
        float e1   = ex2f(sc1 - mx);
        den = den * corr + e0 + e1;
        num = num * corr + e0 * v2.x + e1 * v2.y;
        m = mx;
    }

    out[((size_t)(b * CB + c)) * TB + t] = win[31] + num / den;
}

extern "C" void kernel_launch(void* const* d_in, const int* in_sizes, int n_in,
                              void* d_out, int out_size) {
    const float* x    = (const float*)d_in[0];
    const float* kw   = (const float*)d_in[1];
    const float* kb   = (const float*)d_in[2];
    const float* kg   = (const float*)d_in[3];
    const float* kbe  = (const float*)d_in[4];
    const float* qw   = (const float*)d_in[5];
    const float* qb   = (const float*)d_in[6];
    const float* qg   = (const float*)d_in[7];
    const float* qbe  = (const float*)d_in[8];
    float* o = (float*)d_out;

    dim3 grid(TB, BB);
    csa_kernel<<<grid, 256>>>(x, kw, kb, kg, kbe, qw, qb, qg, qbe, o);
}

// round 2
// speedup vs baseline: 1.2375x; 1.2375x over previous
#include <cuda_runtime.h>
#include <cstdint>

#define CB 256      // channels
#define TB 1024     // time steps
#define BB 4        // batch

#define SKP_ROW 68          // floats per k row (64 data + 4 pad), 272B = 17*16 -> 16B aligned rows
#define SKP_H   (64*SKP_ROW + 8)   // floats per j-half (+32B skew so h0/h1 hit disjoint banks)
#define SV_H    132         // floats per v half (128 + 4 skew)

typedef unsigned long long u64;

// ---- packed fp32x2 helpers (Blackwell) ----
__device__ __forceinline__ u64 dup2(float v) {
    u64 r;
    asm("mov.b64 %0, {%1, %1};" : "=l"(r) : "f"(v));
    return r;
}
__device__ __forceinline__ void unpack2(u64 p, float &lo, float &hi) {
    asm("mov.b64 {%0, %1}, %2;" : "=f"(lo), "=f"(hi) : "l"(p));
}
__device__ __forceinline__ u64 ffma2(u64 a, u64 b, u64 c) {
    u64 d;
    asm("fma.rn.f32x2 %0, %1, %2, %3;" : "=l"(d) : "l"(a), "l"(b), "l"(c));
    return d;
}
__device__ __forceinline__ float ex2f(float v) {
    float y;
    asm("ex2.approx.ftz.f32 %0, %1;" : "=f"(y) : "f"(v));
    return y;
}

// One CTA per (b, t). Phase 1: thread c computes k_c (-> smem pair layout) and q_c.
// Phase 2: thread t = 2p+h owns queries {2p, 2p+1} over j-half h (128 channels).
// Each kk smem load feeds BOTH queries' ffma2 chains (halves LDS vs Round 1).
// Final shfl_xor(1) merges the two j-half flash-softmax partials.
__global__ void __launch_bounds__(256, 1)
csa_kernel(const float* __restrict__ x,
           const float* __restrict__ kw,  const float* __restrict__ kbias,
           const float* __restrict__ kg,  const float* __restrict__ kbeta,
           const float* __restrict__ qw,  const float* __restrict__ qbias,
           const float* __restrict__ qg,  const float* __restrict__ qbeta,
           float* __restrict__ out)
{
    __shared__ __align__(16) float s_wq[32 * 32];   // folded query weights [s][d]
    __shared__ __align__(16) float s_wk[32 * 32];   // folded key   weights [s][d]
    __shared__ float s_bq[32];
    __shared__ float s_bk[32];
    // k pair layout per half h: [j2l][s][p], row stride SKP_ROW, halves skewed by 8 floats
    __shared__ __align__(16) float s_kp[2 * SKP_H];
    __shared__ __align__(8)  float s_v[2 * SV_H];   // xs[b, j, t], halves skewed

    const int t = blockIdx.x;
    const int b = blockIdx.y;
    const int c = threadIdx.x;

    // ---- fold BN into weights/bias ----
    const float inv = rsqrtf(1.0f + 1e-5f);
    for (int idx = c; idx < 32 * 32; idx += 256) {
        int s = idx >> 5;
        s_wq[idx] = qw[idx] * (qg[s] * inv);
        s_wk[idx] = kw[idx] * (kg[s] * inv);
    }
    if (c < 32) {
        s_bq[c] = qbias[c] * (qg[c] * inv) + qbeta[c];
        s_bk[c] = kbias[c] * (kg[c] * inv) + kbeta[c];
    }

    // ---- load causal window into registers (x is L2-resident) ----
    float win[32];
    const float* xrow = x + ((size_t)(b * CB + c)) * TB;
    #pragma unroll
    for (int d = 0; d < 32; d++) {
        int tau = t - 31 + d;
        win[d] = (tau >= 0) ? xrow[tau] : 0.0f;
    }
    s_v[((c >> 7) * SV_H) + (c & 127)] = win[31];
    __syncthreads();

    // ---- key projection -> smem pair layout ----
    {
        const int j2  = c >> 1;
        float* kdst = s_kp + (j2 >> 6) * SKP_H + (j2 & 63) * SKP_ROW + (c & 1);
        #pragma unroll
        for (int s = 0; s < 32; s++) {
            float acc = s_bk[s];
            const float4* wr = (const float4*)(s_wk + s * 32);
            #pragma unroll
            for (int d4 = 0; d4 < 8; d4++) {
                float4 w4 = wr[d4];
                acc += win[4 * d4 + 0] * w4.x;
                acc += win[4 * d4 + 1] * w4.y;
                acc += win[4 * d4 + 2] * w4.z;
                acc += win[4 * d4 + 3] * w4.w;
            }
            kdst[2 * s] = fmaxf(acc, 0.0f);
        }
    }

    // ---- query projection; exchange with pair-partner; dup2 into registers ----
    // qqA = query 2p, qqB = query 2p+1 (both threads of the pair hold both).
    const int h = c & 1;
    u64 qqA[32], qqB[32];
    const float qscale = 0.17677669529663687f * 1.4426950408889634f; // (1/sqrt32)*log2(e)
    #pragma unroll
    for (int s = 0; s < 32; s++) {
        float acc = s_bq[s];
        const float4* wr = (const float4*)(s_wq + s * 32);
        #pragma unroll
        for (int d4 = 0; d4 < 8; d4++) {
            float4 w4 = wr[d4];
            acc += win[4 * d4 + 0] * w4.x;
            acc += win[4 * d4 + 1] * w4.y;
            acc += win[4 * d4 + 2] * w4.z;
            acc += win[4 * d4 + 3] * w4.w;
        }
        float qs = fmaxf(acc, 0.0f) * qscale;          // my query = channel c = 2p+h
        float qp = __shfl_xor_sync(0xffffffffu, qs, 1); // partner query
        float qa = h ? qp : qs;
        float qb = h ? qs : qp;
        qqA[s] = dup2(qa);
        qqB[s] = dup2(qb);
    }
    __syncthreads();

    // ---- ssa + online softmax over this thread's j-half ----
    const float* kbase = s_kp + h * SKP_H;
    const float* vbase = s_v + h * SV_H;
    float mA = -1e30f, dA = 0.0f, nA = 0.0f;
    float mB = -1e30f, dB = 0.0f, nB = 0.0f;
    #pragma unroll 1
    for (int j2 = 0; j2 < 64; j2++) {
        const ulonglong2* kp = (const ulonglong2*)(kbase + j2 * SKP_ROW);
        u64 accA = 0ull, accB = 0ull;
        #pragma unroll
        for (int s2 = 0; s2 < 16; s2++) {
            ulonglong2 kk = kp[s2];      // {k[j0][2s2],k[j1][2s2]},{k[j0][2s2+1],k[j1][2s2+1]}
            accA = ffma2(qqA[2 * s2 + 0], kk.x, accA);
            accA = ffma2(qqA[2 * s2 + 1], kk.y, accA);
            accB = ffma2(qqB[2 * s2 + 0], kk.x, accB);
            accB = ffma2(qqB[2 * s2 + 1], kk.y, accB);
        }
        float2 v2 = *(const float2*)(vbase + 2 * j2);

        float a0, a1, b0, b1;
        unpack2(accA, a0, a1);
        unpack2(accB, b0, b1);

        // query A
        {
            float mx   = fmaxf(mA, fmaxf(a0, a1));
            float corr = ex2f(mA - mx);
            float e0   = ex2f(a0 - mx);
            float e1   = ex2f(a1 - mx);
            dA = dA * corr + e0 + e1;
            nA = nA * corr + e0 * v2.x + e1 * v2.y;
            mA = mx;
        }
        // query B
        {
            float mx   = fmaxf(mB, fmaxf(b0, b1));
            float corr = ex2f(mB - mx);
            float e0   = ex2f(b0 - mx);
            float e1   = ex2f(b1 - mx);
            dB = dB * corr + e0 + e1;
            nB = nB * corr + e0 * v2.x + e1 * v2.y;
            mB = mx;
        }
    }

    // ---- merge the two j-halves (pair partner holds the other half) ----
    float r;
    {
        float pm = __shfl_xor_sync(0xffffffffu, mA, 1);
        float pd = __shfl_xor_sync(0xffffffffu, dA, 1);
        float pn = __shfl_xor_sync(0xffffffffu, nA, 1);
        float M  = fmaxf(mA, pm);
        float ca = ex2f(mA - M), cb = ex2f(pm - M);
        float den = dA * ca + pd * cb;
        float num = nA * ca + pn * cb;
        float rA = num / den;

        pm = __shfl_xor_sync(0xffffffffu, mB, 1);
        pd = __shfl_xor_sync(0xffffffffu, dB, 1);
        pn = __shfl_xor_sync(0xffffffffu, nB, 1);
        M  = fmaxf(mB, pm);
        ca = ex2f(mB - M); cb = ex2f(pm - M);
        den = dB * ca + pd * cb;
        num = nB * ca + pn * cb;
        float rB = num / den;

        r = h ? rB : rA;   // lane h writes query 2p+h (its own channel c)
    }

    const float vc = s_v[((c >> 7) * SV_H) + (c & 127)];
    out[((size_t)(b * CB + c)) * TB + t] = vc + r;
}

extern "C" void kernel_launch(void* const* d_in, const int* in_sizes, int n_in,
                              void* d_out, int out_size) {
    const float* x    = (const float*)d_in[0];
    const float* kw   = (const float*)d_in[1];
    const float* kb   = (const float*)d_in[2];
    const float* kg   = (const float*)d_in[3];
    const float* kbe  = (const float*)d_in[4];
    const float* qw   = (const float*)d_in[5];
    const float* qb   = (const float*)d_in[6];
    const float* qg   = (const float*)d_in[7];
    const float* qbe  = (const float*)d_in[8];
    float* o = (float*)d_out;

    dim3 grid(TB, BB);
    csa_kernel<<<grid, 256>>>(x, kw, kb, kg, kbe, qw, qb, qg, qbe, o);
}

// round 6
// speedup vs baseline: 1.8414x; 1.4880x over previous
#include <cuda_runtime.h>
#include <cuda_bf16.h>
#include <cstdint>

typedef unsigned long long u64;

#define TB 1024
#define BB 4
#define ROWB 80u                 // bytes per bf16 row: 32 bf16 = 64B + 16B pad (conflict-free)
#define ARR  20480u              // 256 * ROWB
#define DSMEM_BYTES (4 * 20480)  // QH | QL | KH | KL

// ---------------- helpers ----------------
static __device__ __forceinline__ u64 pack2(float lo, float hi) {
    u64 r; asm("mov.b64 %0, {%1, %2};" : "=l"(r) : "f"(lo), "f"(hi)); return r;
}
static __device__ __forceinline__ void unpack2(u64 p, float& lo, float& hi) {
    asm("mov.b64 {%0, %1}, %2;" : "=f"(lo), "=f"(hi) : "l"(p));
}
static __device__ __forceinline__ u64 ffma2(u64 a, u64 b, u64 c) {
    u64 d; asm("fma.rn.f32x2 %0, %1, %2, %3;" : "=l"(d) : "l"(a), "l"(b), "l"(c)); return d;
}
static __device__ __forceinline__ float ex2f(float v) {
    float y; asm("ex2.approx.ftz.f32 %0, %1;" : "=f"(y) : "f"(v)); return y;
}
static __device__ __forceinline__ float dot32(const float* wrow, const u64* win2) {
    u64 acc = 0ull;
    const ulonglong2* w2 = (const ulonglong2*)wrow;
    #pragma unroll
    for (int i = 0; i < 8; i++) {
        ulonglong2 w = w2[i];
        acc = ffma2(win2[2 * i + 0], w.x, acc);
        acc = ffma2(win2[2 * i + 1], w.y, acc);
    }
    float lo, hi; unpack2(acc, lo, hi);
    return lo + hi;
}
static __device__ __forceinline__ void bsplit(float v, uint16_t& hi, uint16_t& lo) {
    __nv_bfloat16 h = __float2bfloat16(v);
    __nv_bfloat16 l = __float2bfloat16(v - __bfloat162float(h));
    hi = __bfloat16_as_ushort(h);
    lo = __bfloat16_as_ushort(l);
}
// m16n8k16 row.col f32.bf16.bf16.f32, D += A*B
static __device__ __forceinline__ void mma16816(float* d, const uint32_t* a, const uint32_t* b) {
    asm("mma.sync.aligned.m16n8k16.row.col.f32.bf16.bf16.f32 "
        "{%0,%1,%2,%3}, {%4,%5,%6,%7}, {%8,%9}, {%0,%1,%2,%3};"
        : "+f"(d[0]), "+f"(d[1]), "+f"(d[2]), "+f"(d[3])
        : "r"(a[0]), "r"(a[1]), "r"(a[2]), "r"(a[3]), "r"(b[0]), "r"(b[1]));
}

// ---------------- kernel ----------------
// One CTA per (b,t), 256 threads, 2 CTAs/SM.
// Phase 1 (FFMA): thread c computes q_c[32], k_c[32]; bf16 hi/lo split -> smem rows.
// Phase 2 (HMMA): warp w: rows 32w..32w+31 (2 m16 tiles) x 256 cols in 16 chunks of 16.
//   score = qh*kh + qh*kl + ql*kh (exact to ~1e-5). Flash softmax in registers,
//   quad shfl merge at the end, out = x + num/den.
__global__ void __launch_bounds__(256, 2)
csa_mma_kernel(const float* __restrict__ x,
               const float* __restrict__ kw,  const float* __restrict__ kbias,
               const float* __restrict__ kg,  const float* __restrict__ kbeta,
               const float* __restrict__ qw,  const float* __restrict__ qbias,
               const float* __restrict__ qg,  const float* __restrict__ qbeta,
               float* __restrict__ out)
{
    extern __shared__ char dsm[];
    __shared__ __align__(16) float s_wq[32 * 32];
    __shared__ __align__(16) float s_wk[32 * 32];
    __shared__ float s_bq[32], s_bk[32];
    __shared__ __align__(8) float s_v[256];

    char* QH = dsm;
    char* QL = dsm + ARR;
    char* KH = dsm + 2 * ARR;
    char* KL = dsm + 3 * ARR;

    const int t   = blockIdx.x;
    const int b   = blockIdx.y;
    const int tid = threadIdx.x;
    const int w   = tid >> 5;
    const int l   = tid & 31;
    const int g   = l >> 2;    // row group within fragment
    const int cq  = l & 3;     // quad col id

    // ---- fold BN into weights/bias ----
    const float inv = rsqrtf(1.0f + 1e-5f);
    for (int i = tid; i < 32 * 32; i += 256) {
        int s = i >> 5;
        s_wq[i] = qw[i] * (qg[s] * inv);
        s_wk[i] = kw[i] * (kg[s] * inv);
    }
    if (tid < 32) {
        s_bq[tid] = qbias[tid] * (qg[tid] * inv) + qbeta[tid];
        s_bk[tid] = kbias[tid] * (kg[tid] * inv) + kbeta[tid];
    }

    // ---- causal window (x is L2-resident) ----
    float win[32];
    {
        const float* xrow = x + ((size_t)(b * 256 + tid)) * TB;
        #pragma unroll
        for (int d = 0; d < 32; d++) {
            int tau = t - 31 + d;
            win[d] = (tau >= 0) ? xrow[tau] : 0.0f;
        }
    }
    s_v[tid] = win[31];
    __syncthreads();

    // ---- projections + bf16 split -> smem ----
    {
        u64 win2[16];
        #pragma unroll
        for (int i = 0; i < 16; i++) win2[i] = pack2(win[2 * i], win[2 * i + 1]);

        const float qscale = 0.17677669529663687f * 1.4426950408889634f; // (1/sqrt32)*log2(e)
        uint32_t qhp[16], qlp[16], khp[16], klp[16];
        #pragma unroll
        for (int s2 = 0; s2 < 16; s2++) {
            int sA = 2 * s2, sB = sA + 1;
            float qa = fmaxf(dot32(s_wq + sA * 32, win2) + s_bq[sA], 0.0f) * qscale;
            float qb = fmaxf(dot32(s_wq + sB * 32, win2) + s_bq[sB], 0.0f) * qscale;
            float ka = fmaxf(dot32(s_wk + sA * 32, win2) + s_bk[sA], 0.0f);
            float kb = fmaxf(dot32(s_wk + sB * 32, win2) + s_bk[sB], 0.0f);
            uint16_t h0, l0, h1, l1;
            bsplit(qa, h0, l0); bsplit(qb, h1, l1);
            qhp[s2] = (uint32_t)h0 | ((uint32_t)h1 << 16);
            qlp[s2] = (uint32_t)l0 | ((uint32_t)l1 << 16);
            bsplit(ka, h0, l0); bsplit(kb, h1, l1);
            khp[s2] = (uint32_t)h0 | ((uint32_t)h1 << 16);
            klp[s2] = (uint32_t)l0 | ((uint32_t)l1 << 16);
        }
        uint4* qhr = (uint4*)(QH + tid * ROWB);
        uint4* qlr = (uint4*)(QL + tid * ROWB);
        uint4* khr = (uint4*)(KH + tid * ROWB);
        uint4* klr = (uint4*)(KL + tid * ROWB);
        #pragma unroll
        for (int i = 0; i < 4; i++) {
            qhr[i] = make_uint4(qhp[4*i], qhp[4*i+1], qhp[4*i+2], qhp[4*i+3]);
            qlr[i] = make_uint4(qlp[4*i], qlp[4*i+1], qlp[4*i+2], qlp[4*i+3]);
            khr[i] = make_uint4(khp[4*i], khp[4*i+1], khp[4*i+2], khp[4*i+3]);
            klr[i] = make_uint4(klp[4*i], klp[4*i+1], klp[4*i+2], klp[4*i+3]);
        }
    }
    __syncthreads();

    // ---- A fragments (held whole loop): [mt][khalf][4] for qh and ql ----
    uint32_t aqh[2][2][4], aql[2][2][4];
    #pragma unroll
    for (int mt = 0; mt < 2; mt++) {
        uint32_t rowb = (uint32_t)(32 * w + 16 * mt + g) * ROWB + (uint32_t)cq * 4u;
        #pragma unroll
        for (int k2 = 0; k2 < 2; k2++) {
            uint32_t off = rowb + (uint32_t)k2 * 32u;
            aqh[mt][k2][0] = *(const uint32_t*)(QH + off);
            aqh[mt][k2][1] = *(const uint32_t*)(QH + off + 8 * ROWB);
            aqh[mt][k2][2] = *(const uint32_t*)(QH + off + 16);
            aqh[mt][k2][3] = *(const uint32_t*)(QH + off + 8 * ROWB + 16);
            aql[mt][k2][0] = *(const uint32_t*)(QL + off);
            aql[mt][k2][1] = *(const uint32_t*)(QL + off + 8 * ROWB);
            aql[mt][k2][2] = *(const uint32_t*)(QL + off + 16);
            aql[mt][k2][3] = *(const uint32_t*)(QL + off + 8 * ROWB + 16);
        }
    }

    float stM[4], stD[4], stN[4];
    #pragma unroll
    for (int r = 0; r < 4; r++) { stM[r] = -1e30f; stD[r] = 0.0f; stN[r] = 0.0f; }

    const char* bh_base = KH + (uint32_t)g * ROWB + (uint32_t)cq * 4u;
    const char* bl_base = KL + (uint32_t)g * ROWB + (uint32_t)cq * 4u;

    #pragma unroll 1
    for (int ch = 0; ch < 16; ch++) {
        const char* bhp = bh_base + (uint32_t)(16 * ch) * ROWB;
        const char* blp = bl_base + (uint32_t)(16 * ch) * ROWB;

        uint32_t bh[2][2][2], bl[2][2][2];   // [ntile][khalf][reg]
        #pragma unroll
        for (int nt = 0; nt < 2; nt++) {
            uint32_t noff = (uint32_t)nt * 8u * ROWB;
            #pragma unroll
            for (int k2 = 0; k2 < 2; k2++) {
                uint32_t off = noff + (uint32_t)k2 * 32u;
                bh[nt][k2][0] = *(const uint32_t*)(bhp + off);
                bh[nt][k2][1] = *(const uint32_t*)(bhp + off + 16);
                bl[nt][k2][0] = *(const uint32_t*)(blp + off);
                bl[nt][k2][1] = *(const uint32_t*)(blp + off + 16);
            }
        }
        float2 v0 = *(const float2*)&s_v[16 * ch + 2 * cq];
        float2 v1 = *(const float2*)&s_v[16 * ch + 8 + 2 * cq];

        float acc[2][2][4];
        #pragma unroll
        for (int mt = 0; mt < 2; mt++)
            #pragma unroll
            for (int nt = 0; nt < 2; nt++) {
                acc[mt][nt][0] = acc[mt][nt][1] = acc[mt][nt][2] = acc[mt][nt][3] = 0.0f;
                mma16816(acc[mt][nt], aqh[mt][0], bh[nt][0]);   // qh*kh k0
                mma16816(acc[mt][nt], aqh[mt][1], bh[nt][1]);   // qh*kh k1
                mma16816(acc[mt][nt], aqh[mt][0], bl[nt][0]);   // qh*kl k0
                mma16816(acc[mt][nt], aqh[mt][1], bl[nt][1]);   // qh*kl k1
                mma16816(acc[mt][nt], aql[mt][0], bh[nt][0]);   // ql*kh k0
                mma16816(acc[mt][nt], aql[mt][1], bh[nt][1]);   // ql*kh k1
            }

        // flash update: 4 logical rows per thread (mt x row-half), 4 cols each
        #pragma unroll
        for (int mt = 0; mt < 2; mt++)
            #pragma unroll
            for (int i = 0; i < 2; i++) {
                int r = mt * 2 + i;
                float s0 = acc[mt][0][2 * i + 0];
                float s1 = acc[mt][0][2 * i + 1];
                float s2 = acc[mt][1][2 * i + 0];
                float s3 = acc[mt][1][2 * i + 1];
                float mx = fmaxf(fmaxf(s0, s1), fmaxf(s2, s3));
                float Mn = fmaxf(stM[r], mx);
                float corr = ex2f(stM[r] - Mn);
                float e0 = ex2f(s0 - Mn);
                float e1 = ex2f(s1 - Mn);
                float e2 = ex2f(s2 - Mn);
                float e3 = ex2f(s3 - Mn);
                stD[r] = stD[r] * corr + ((e0 + e1) + (e2 + e3));
                stN[r] = stN[r] * corr + (e0 * v0.x + e1 * v0.y + e2 * v1.x + e3 * v1.y);
                stM[r] = Mn;
            }
    }

    // ---- quad merge (cols) + write ----
    #pragma unroll
    for (int r = 0; r < 4; r++) {
        #pragma unroll
        for (int off = 1; off <= 2; off <<= 1) {
            float pm = __shfl_xor_sync(0xffffffffu, stM[r], off);
            float pd = __shfl_xor_sync(0xffffffffu, stD[r], off);
            float pn = __shfl_xor_sync(0xffffffffu, stN[r], off);
            float M  = fmaxf(stM[r], pm);
            float ca = ex2f(stM[r] - M), cb = ex2f(pm - M);
            stD[r] = stD[r] * ca + pd * cb;
            stN[r] = stN[r] * ca + pn * cb;
            stM[r] = M;
        }
    }
    if (cq == 0) {
        #pragma unroll
        for (int r = 0; r < 4; r++) {
            int row = 32 * w + (r >> 1) * 16 + (r & 1) * 8 + g;
            out[((size_t)(b * 256 + row)) * TB + t] = s_v[row] + stN[r] / stD[r];
        }
    }
}

extern "C" void kernel_launch(void* const* d_in, const int* in_sizes, int n_in,
                              void* d_out, int out_size) {
    const float* x    = (const float*)d_in[0];
    const float* kw   = (const float*)d_in[1];
    const float* kb   = (const float*)d_in[2];
    const float* kg   = (const float*)d_in[3];
    const float* kbe  = (const float*)d_in[4];
    const float* qw   = (const float*)d_in[5];
    const float* qb   = (const float*)d_in[6];
    const float* qg   = (const float*)d_in[7];
    const float* qbe  = (const float*)d_in[8];
    float* o = (float*)d_out;

    cudaFuncSetAttribute(csa_mma_kernel, cudaFuncAttributeMaxDynamicSharedMemorySize, DSMEM_BYTES);
    dim3 grid(TB, BB);
    csa_mma_kernel<<<grid, 256, DSMEM_BYTES>>>(x, kw, kb, kg, kbe, qw, qb, qg, qbe, o);
}